// round 1
// baseline (speedup 1.0000x reference)
#include <cuda_runtime.h>
#include <cstdint>

#define BB 64
#define NN 10000
#define LL 50
#define DD 512
#define OO 7
#define KNB 10
#define NGRP 5        // ligand groups per batch (10 ligs each)
#define GL 10         // ligs per group (held in registers)
#define NCHUNK 4
#define CHUNK 2500    // NN / NCHUNK
#define CAP 1024

// -------- device scratch (no allocations allowed) --------
__device__ unsigned char g_mask[BB * NN];
__device__ unsigned int  g_T0[BB * LL];
__device__ int           g_cnt[BB * LL];
__device__ unsigned long long g_cand[(size_t)BB * LL * CAP];

// order-preserving float<->uint transform (handles negative keys)
__device__ __forceinline__ unsigned encf(float f) {
    unsigned u = __float_as_uint(f);
    return (u & 0x80000000u) ? ~u : (u | 0x80000000u);
}
__device__ __forceinline__ float decf(unsigned u) {
    return (u & 0x80000000u) ? __uint_as_float(u & 0x7fffffffu)
                             : __uint_as_float(~u);
}
// key = 0.5*|p|^2 - p.l  (order-equivalent to |p-l|^2 for fixed l)
// MUST be bit-identical across kernels -> explicit rn intrinsics.
__device__ __forceinline__ float qof(float px, float py, float pz) {
    return 0.5f * __fmaf_rn(pz, pz, __fmaf_rn(py, py, __fmul_rn(px, px)));
}
__device__ __forceinline__ float keyf(float px, float py, float pz, float q,
                                      float lx, float ly, float lz) {
    return __fmaf_rn(pz, -lz, __fmaf_rn(py, -ly, __fmaf_rn(px, -lx, q)));
}

// -------- K0: init scratch --------
__global__ void k_init() {
    int i = blockIdx.x * blockDim.x + threadIdx.x;
    if (i < (BB * NN) / 4) reinterpret_cast<unsigned*>(g_mask)[i] = 0u;
    if (i < BB * LL) { g_T0[i] = 0xFFFFFFFFu; g_cnt[i] = 0; }
}

// -------- K1: per-(b,lig) threshold = min over chunks of
//          (10th-smallest of 32 lane minima) --------
__global__ void k_thresh(const float* __restrict__ pos,
                         const float* __restrict__ lig) {
    int wg   = (blockIdx.x * blockDim.x + threadIdx.x) >> 5;
    int lane = threadIdx.x & 31;
    int b    = wg / (NGRP * NCHUNK);
    int r    = wg % (NGRP * NCHUNK);
    int grp  = r / NCHUNK;
    int ch   = r % NCHUNK;

    float lx[GL], ly[GL], lz[GL], m[GL];
    const float* lp = lig + ((size_t)b * LL + grp * GL) * 3;
#pragma unroll
    for (int j = 0; j < GL; j++) {
        lx[j] = lp[j * 3 + 0]; ly[j] = lp[j * 3 + 1]; lz[j] = lp[j * 3 + 2];
        m[j] = 3.4e38f;
    }
    const float* pp = pos + (size_t)b * NN * 3;
    int i0 = ch * CHUNK, i1 = i0 + CHUNK;
    for (int i = i0 + lane; i < i1; i += 32) {
        float px = pp[i * 3 + 0], py = pp[i * 3 + 1], pz = pp[i * 3 + 2];
        float q = qof(px, py, pz);
#pragma unroll
        for (int j = 0; j < GL; j++)
            m[j] = fminf(m[j], keyf(px, py, pz, q, lx[j], ly[j], lz[j]));
    }
#pragma unroll
    for (int j = 0; j < GL; j++) {
        float v = m[j], w = v;
#pragma unroll
        for (int t = 0; t < KNB; t++) {
            w = v;
#pragma unroll
            for (int o = 16; o; o >>= 1)
                w = fminf(w, __shfl_xor_sync(0xffffffffu, w, o));
            if (t < KNB - 1) {
                unsigned bal = __ballot_sync(0xffffffffu, v == w);
                if (lane == __ffs(bal) - 1) v = 3.4e38f;  // knock out one owner
            }
        }
        if (lane == 0)
            atomicMin(&g_T0[b * LL + grp * GL + j], encf(w));
    }
}

// -------- K2: collect all candidates with key <= T0 --------
__global__ void k_collect(const float* __restrict__ pos,
                          const float* __restrict__ lig) {
    int wg   = (blockIdx.x * blockDim.x + threadIdx.x) >> 5;
    int lane = threadIdx.x & 31;
    int b    = wg / (NGRP * NCHUNK);
    int r    = wg % (NGRP * NCHUNK);
    int grp  = r / NCHUNK;
    int ch   = r % NCHUNK;

    float lx[GL], ly[GL], lz[GL], t[GL];
    const float* lp = lig + ((size_t)b * LL + grp * GL) * 3;
#pragma unroll
    for (int j = 0; j < GL; j++) {
        lx[j] = lp[j * 3 + 0]; ly[j] = lp[j * 3 + 1]; lz[j] = lp[j * 3 + 2];
        t[j]  = decf(g_T0[b * LL + grp * GL + j]);
    }
    const float* pp = pos + (size_t)b * NN * 3;
    int i0 = ch * CHUNK, i1 = i0 + CHUNK;
    for (int i = i0 + lane; i < i1; i += 32) {
        float px = pp[i * 3 + 0], py = pp[i * 3 + 1], pz = pp[i * 3 + 2];
        float q = qof(px, py, pz);
#pragma unroll
        for (int j = 0; j < GL; j++) {
            float key = keyf(px, py, pz, q, lx[j], ly[j], lz[j]);
            if (key <= t[j]) {
                int pairid = b * LL + grp * GL + j;
                int s = atomicAdd(&g_cnt[pairid], 1);
                if (s < CAP)
                    g_cand[(size_t)pairid * CAP + s] =
                        ((unsigned long long)encf(key) << 32) | (unsigned)i;
            }
        }
    }
}

// -------- K3: exact top-10 among candidates -> set mask --------
__global__ void k_select(const float* __restrict__ pos,
                         const float* __restrict__ lig) {
    int wg   = (blockIdx.x * blockDim.x + threadIdx.x) >> 5;
    int lane = threadIdx.x & 31;
    if (wg >= BB * LL) return;
    int b = wg / LL, l = wg % LL;

    unsigned long long hp[KNB];
#pragma unroll
    for (int j = 0; j < KNB; j++) hp[j] = ~0ull;

    int cnt = g_cnt[wg];
    if (cnt <= CAP) {
        for (int s = lane; s < cnt; s += 32) {
            unsigned long long v = g_cand[(size_t)wg * CAP + s];
            if (v < hp[KNB - 1]) {
#pragma unroll
                for (int j = 0; j < KNB; j++)
                    if (v < hp[j]) { unsigned long long tm = hp[j]; hp[j] = v; v = tm; }
            }
        }
    } else {
        // fallback: exact rescan of all N points (never expected to trigger)
        const float* lp = lig + ((size_t)b * LL + l) * 3;
        float lx = lp[0], ly = lp[1], lz = lp[2];
        const float* pp = pos + (size_t)b * NN * 3;
        for (int i = lane; i < NN; i += 32) {
            float px = pp[i * 3 + 0], py = pp[i * 3 + 1], pz = pp[i * 3 + 2];
            float q = qof(px, py, pz);
            unsigned long long v =
                ((unsigned long long)encf(keyf(px, py, pz, q, lx, ly, lz)) << 32) |
                (unsigned)i;
            if (v < hp[KNB - 1]) {
#pragma unroll
                for (int j = 0; j < KNB; j++)
                    if (v < hp[j]) { unsigned long long tm = hp[j]; hp[j] = v; v = tm; }
            }
        }
    }

    // merge sorted per-lane lists: 10 rounds of warp-argmin + advance
    unsigned long long cur = hp[0];
#pragma unroll
    for (int rr = 0; rr < KNB; rr++) {
        unsigned long long w = cur;
#pragma unroll
        for (int o = 16; o; o >>= 1) {
            unsigned long long ov = __shfl_xor_sync(0xffffffffu, w, o);
            w = (ov < w) ? ov : w;
        }
        if (lane == 0 && w != ~0ull)
            g_mask[b * NN + (unsigned)(w & 0xffffffffu)] = 1;
        if (cur == w) {   // unique owner (idx in low bits is unique)
#pragma unroll
            for (int j = 0; j < KNB - 1; j++) hp[j] = hp[j + 1];
            hp[KNB - 1] = ~0ull;
            cur = hp[0];
        }
    }
}

// -------- block-wide sum over 512 threads --------
__device__ __forceinline__ float block_sum512(float v, float* s_red) {
    int tid = threadIdx.x;
#pragma unroll
    for (int o = 16; o; o >>= 1) v += __shfl_xor_sync(0xffffffffu, v, o);
    if ((tid & 31) == 0) s_red[tid >> 5] = v;
    __syncthreads();
    if (tid < 16) {
        float r = s_red[tid];
#pragma unroll
        for (int o = 8; o; o >>= 1) r += __shfl_xor_sync(0x0000ffffu, r, o);
        if (tid == 0) s_red[0] = r;
    }
    __syncthreads();
    float r = s_red[0];
    __syncthreads();  // allow s_red reuse
    return r;
}

// -------- K4: pool (masked mean via gather) + MLP + LN + SiLU + head --------
__global__ void __launch_bounds__(DD)
k_poolmlp(const float* __restrict__ x,  const float* __restrict__ W1,
          const float* __restrict__ b1, const float* __restrict__ gamma,
          const float* __restrict__ beta, const float* __restrict__ W2,
          const float* __restrict__ b2, float* __restrict__ out) {
    int b = blockIdx.x, tid = threadIdx.x;
    __shared__ int   s_sel[LL * KNB];
    __shared__ int   s_cnt;
    __shared__ float s_v[DD];
    __shared__ float s_red[16];
    __shared__ float s_part[16][OO];

    // deterministic compaction of mask -> index list (warp 0)
    if (tid < 32) {
        int off = 0;
        const unsigned char* mb = g_mask + (size_t)b * NN;
        for (int base = 0; base < NN; base += 32) {
            int i = base + tid;
            bool f = (i < NN) && mb[i];
            unsigned bal = __ballot_sync(0xffffffffu, f);
            if (f) s_sel[off + __popc(bal & ((1u << tid) - 1u))] = i;
            off += __popc(bal);
        }
        if (tid == 0) s_cnt = off;
    }
    __syncthreads();
    int cnt = s_cnt;

    // masked mean: gather selected rows of x
    const float* xb = x + (size_t)b * NN * DD;
    float a0 = 0.f, a1 = 0.f, a2 = 0.f, a3 = 0.f;
    int j = 0;
    for (; j + 4 <= cnt; j += 4) {
        a0 += xb[(size_t)s_sel[j + 0] * DD + tid];
        a1 += xb[(size_t)s_sel[j + 1] * DD + tid];
        a2 += xb[(size_t)s_sel[j + 2] * DD + tid];
        a3 += xb[(size_t)s_sel[j + 3] * DD + tid];
    }
    for (; j < cnt; ++j) a0 += xb[(size_t)s_sel[j] * DD + tid];
    float emb = (a0 + a1 + a2 + a3) / (float)cnt;
    s_v[tid] = emb;
    __syncthreads();

    // h = emb @ W1 + b1   (thread = output dim, coalesced W1 column access)
    float h = b1[tid];
#pragma unroll 8
    for (int k = 0; k < DD; k++)
        h = __fmaf_rn(s_v[k], W1[k * DD + tid], h);

    // LayerNorm (two-pass for stability)
    float mu  = block_sum512(h, s_red) * (1.0f / DD);
    float dv  = h - mu;
    float var = block_sum512(dv * dv, s_red) * (1.0f / DD);
    float vn  = dv * rsqrtf(var + 1e-5f) * gamma[tid] + beta[tid];
    float act = vn / (1.0f + __expf(-vn));  // SiLU

    // out = act @ W2 + b2  (deterministic tree reduction)
    float p[OO];
#pragma unroll
    for (int o = 0; o < OO; o++) p[o] = act * W2[tid * OO + o];
#pragma unroll
    for (int o = 0; o < OO; o++)
#pragma unroll
        for (int of = 16; of; of >>= 1)
            p[o] += __shfl_xor_sync(0xffffffffu, p[o], of);
    if ((tid & 31) == 0) {
#pragma unroll
        for (int o = 0; o < OO; o++) s_part[tid >> 5][o] = p[o];
    }
    __syncthreads();
    if (tid < OO) {
        float s = 0.f;
#pragma unroll
        for (int w = 0; w < 16; w++) s += s_part[w][tid];
        out[b * OO + tid] = s + b2[tid];
    }
}

extern "C" void kernel_launch(void* const* d_in, const int* in_sizes, int n_in,
                              void* d_out, int out_size) {
    const float* pos   = (const float*)d_in[0];
    const float* x     = (const float*)d_in[1];
    const float* lig   = (const float*)d_in[2];
    const float* W1    = (const float*)d_in[3];
    const float* b1    = (const float*)d_in[4];
    const float* gamma = (const float*)d_in[5];
    const float* beta  = (const float*)d_in[6];
    const float* W2    = (const float*)d_in[7];
    const float* b2    = (const float*)d_in[8];
    float* out = (float*)d_out;

    k_init<<<640, 256>>>();
    k_thresh<<<(BB * NGRP * NCHUNK * 32) / 256, 256>>>(pos, lig);   // 160 blocks
    k_collect<<<(BB * NGRP * NCHUNK * 32) / 256, 256>>>(pos, lig);  // 160 blocks
    k_select<<<(BB * LL * 32) / 256, 256>>>(pos, lig);              // 400 blocks
    k_poolmlp<<<BB, DD>>>(x, W1, b1, gamma, beta, W2, b2, out);
}

// round 2
// speedup vs baseline: 1.9796x; 1.9796x over previous
#include <cuda_runtime.h>
#include <cstdint>

#define BB 64
#define NN 10000
#define LL 50
#define DD 512
#define OO 7
#define KNB 10
#define NGRP 5        // ligand groups per batch (10 ligs each)
#define GL 10         // ligs per group (held in registers)
#define NCHUNK 10
#define CHUNK 1000    // NN / NCHUNK
#define CAP 512
#define NWORD 313     // ceil(NN/32)

// -------- device scratch (no allocations allowed) --------
__device__ unsigned int  g_T0[BB * LL];
__device__ int           g_cnt[BB * LL];
__device__ unsigned long long g_cand[(size_t)BB * LL * CAP];
__device__ int           g_sel10[BB * LL * KNB];
__device__ int           g_sellist[BB * 512];
__device__ int           g_ucnt[BB];
__device__ float         g_part[BB * 4 * DD];

// order-preserving float<->uint transform (handles negative keys)
__device__ __forceinline__ unsigned encf(float f) {
    unsigned u = __float_as_uint(f);
    return (u & 0x80000000u) ? ~u : (u | 0x80000000u);
}
__device__ __forceinline__ float decf(unsigned u) {
    return (u & 0x80000000u) ? __uint_as_float(u & 0x7fffffffu)
                             : __uint_as_float(~u);
}
// key = 0.5*|p|^2 - p.l  (order-equivalent to |p-l|^2 for fixed l)
// MUST be bit-identical across kernels -> explicit rn intrinsics.
__device__ __forceinline__ float qof(float px, float py, float pz) {
    return 0.5f * __fmaf_rn(pz, pz, __fmaf_rn(py, py, __fmul_rn(px, px)));
}
__device__ __forceinline__ float keyf(float px, float py, float pz, float q,
                                      float lx, float ly, float lz) {
    return __fmaf_rn(pz, -lz, __fmaf_rn(py, -ly, __fmaf_rn(px, -lx, q)));
}

// full 32-lane bitonic sort (ascending); returns this lane's sorted value
__device__ __forceinline__ float warp_bitonic_sort(float v, int lane) {
#pragma unroll
    for (int k = 2; k <= 32; k <<= 1) {
#pragma unroll
        for (int j = k >> 1; j; j >>= 1) {
            float o = __shfl_xor_sync(0xffffffffu, v, j);
            bool keepMin = (((lane & j) == 0) == ((lane & k) == 0));
            v = keepMin ? fminf(v, o) : fmaxf(v, o);
        }
    }
    return v;
}

// -------- K0: init scratch --------
__global__ void k_init() {
    int i = blockIdx.x * blockDim.x + threadIdx.x;
    if (i < BB * LL) { g_T0[i] = 0xFFFFFFFFu; g_cnt[i] = 0; }
}

// -------- K1: per-(b,lig) threshold = min over chunks of
//          (exact 10th-smallest of the 32 lane minima) --------
__global__ void k_thresh(const float* __restrict__ pos,
                         const float* __restrict__ lig) {
    int wg   = (blockIdx.x * blockDim.x + threadIdx.x) >> 5;
    int lane = threadIdx.x & 31;
    int b    = wg / (NGRP * NCHUNK);
    int r    = wg % (NGRP * NCHUNK);
    int grp  = r / NCHUNK;
    int ch   = r % NCHUNK;

    float lx[GL], ly[GL], lz[GL], m[GL];
    const float* lp = lig + ((size_t)b * LL + grp * GL) * 3;
#pragma unroll
    for (int j = 0; j < GL; j++) {
        lx[j] = lp[j * 3 + 0]; ly[j] = lp[j * 3 + 1]; lz[j] = lp[j * 3 + 2];
        m[j] = 3.4e38f;
    }
    const float* pp = pos + (size_t)b * NN * 3;
    int i0 = ch * CHUNK, i1 = i0 + CHUNK;
    for (int i = i0 + lane; i < i1; i += 32) {
        float px = pp[i * 3 + 0], py = pp[i * 3 + 1], pz = pp[i * 3 + 2];
        float q = qof(px, py, pz);
#pragma unroll
        for (int j = 0; j < GL; j++)
            m[j] = fminf(m[j], keyf(px, py, pz, q, lx[j], ly[j], lz[j]));
    }
    // provable upper bound on this chunk's 10th smallest:
    // 10 distinct lanes (=> 10 distinct points) have minima <= sorted[9]
#pragma unroll
    for (int j = 0; j < GL; j++) {
        float sv = warp_bitonic_sort(m[j], lane);
        float w  = __shfl_sync(0xffffffffu, sv, KNB - 1);
        if (lane == 0)
            atomicMin(&g_T0[b * LL + grp * GL + j], encf(w));
    }
}

// -------- K2: collect all candidates with key <= T0 --------
__global__ void k_collect(const float* __restrict__ pos,
                          const float* __restrict__ lig) {
    int wg   = (blockIdx.x * blockDim.x + threadIdx.x) >> 5;
    int lane = threadIdx.x & 31;
    int b    = wg / (NGRP * NCHUNK);
    int r    = wg % (NGRP * NCHUNK);
    int grp  = r / NCHUNK;
    int ch   = r % NCHUNK;

    float lx[GL], ly[GL], lz[GL], t[GL];
    const float* lp = lig + ((size_t)b * LL + grp * GL) * 3;
#pragma unroll
    for (int j = 0; j < GL; j++) {
        lx[j] = lp[j * 3 + 0]; ly[j] = lp[j * 3 + 1]; lz[j] = lp[j * 3 + 2];
        t[j]  = decf(g_T0[b * LL + grp * GL + j]);
    }
    const float* pp = pos + (size_t)b * NN * 3;
    int i0 = ch * CHUNK, i1 = i0 + CHUNK;
    for (int i = i0 + lane; i < i1; i += 32) {
        float px = pp[i * 3 + 0], py = pp[i * 3 + 1], pz = pp[i * 3 + 2];
        float q = qof(px, py, pz);
#pragma unroll
        for (int j = 0; j < GL; j++) {
            float key = keyf(px, py, pz, q, lx[j], ly[j], lz[j]);
            if (key <= t[j]) {
                int pairid = b * LL + grp * GL + j;
                int s = atomicAdd(&g_cnt[pairid], 1);
                if (s < CAP)
                    g_cand[(size_t)pairid * CAP + s] =
                        ((unsigned long long)encf(key) << 32) | (unsigned)i;
            }
        }
    }
}

// -------- K3: exact top-10 among candidates -> emit 10 indices --------
__global__ void k_select(const float* __restrict__ pos,
                         const float* __restrict__ lig) {
    int wg   = (blockIdx.x * blockDim.x + threadIdx.x) >> 5;
    int lane = threadIdx.x & 31;
    if (wg >= BB * LL) return;
    int b = wg / LL, l = wg % LL;

    unsigned long long hp[KNB];
#pragma unroll
    for (int j = 0; j < KNB; j++) hp[j] = ~0ull;

    int cnt = g_cnt[wg];
    if (cnt <= CAP) {
        for (int s = lane; s < cnt; s += 32) {
            unsigned long long v = g_cand[(size_t)wg * CAP + s];
            if (v < hp[KNB - 1]) {
#pragma unroll
                for (int j = 0; j < KNB; j++)
                    if (v < hp[j]) { unsigned long long tm = hp[j]; hp[j] = v; v = tm; }
            }
        }
    } else {
        // fallback: exact rescan of all N points (never expected to trigger)
        const float* lp = lig + ((size_t)b * LL + l) * 3;
        float lx = lp[0], ly = lp[1], lz = lp[2];
        const float* pp = pos + (size_t)b * NN * 3;
        for (int i = lane; i < NN; i += 32) {
            float px = pp[i * 3 + 0], py = pp[i * 3 + 1], pz = pp[i * 3 + 2];
            float q = qof(px, py, pz);
            unsigned long long v =
                ((unsigned long long)encf(keyf(px, py, pz, q, lx, ly, lz)) << 32) |
                (unsigned)i;
            if (v < hp[KNB - 1]) {
#pragma unroll
                for (int j = 0; j < KNB; j++)
                    if (v < hp[j]) { unsigned long long tm = hp[j]; hp[j] = v; v = tm; }
            }
        }
    }

    // merge sorted per-lane lists: 10 rounds of warp-argmin + advance
    unsigned long long cur = hp[0];
#pragma unroll
    for (int rr = 0; rr < KNB; rr++) {
        unsigned long long w = cur;
#pragma unroll
        for (int o = 16; o; o >>= 1) {
            unsigned long long ov = __shfl_xor_sync(0xffffffffu, w, o);
            w = (ov < w) ? ov : w;
        }
        if (lane == 0)
            g_sel10[wg * KNB + rr] = (int)(unsigned)(w & 0xffffffffu);
        if (cur == w) {   // unique owner (idx in low bits is unique)
#pragma unroll
            for (int j = 0; j < KNB - 1; j++) hp[j] = hp[j + 1];
            hp[KNB - 1] = ~0ull;
            cur = hp[0];
        }
    }
}

// -------- K4: dedupe 500 indices -> compact unique list (deterministic) ----
__global__ void __launch_bounds__(512)
k_compact() {
    int b = blockIdx.x, tid = threadIdx.x;
    int lane = tid & 31, wid = tid >> 5;
    __shared__ unsigned bits[320];
    __shared__ int wsum[16];
    __shared__ int s_total;

    if (tid < 320) bits[tid] = 0u;
    __syncthreads();
    if (tid < LL * KNB) {
        unsigned idx = (unsigned)g_sel10[b * LL * KNB + tid];
        atomicOr(&bits[idx >> 5], 1u << (idx & 31));
    }
    __syncthreads();

    int c = (tid < NWORD) ? __popc(bits[tid]) : 0;
    int sc = c;  // inclusive warp scan
#pragma unroll
    for (int o = 1; o < 32; o <<= 1) {
        int n = __shfl_up_sync(0xffffffffu, sc, o);
        if (lane >= o) sc += n;
    }
    if (lane == 31) wsum[wid] = sc;
    __syncthreads();
    if (tid < 16) {
        int w = wsum[tid], sw = w;
#pragma unroll
        for (int o = 1; o < 16; o <<= 1) {
            int n = __shfl_up_sync(0x0000ffffu, sw, o);
            if (tid >= o) sw += n;
        }
        wsum[tid] = sw - w;               // exclusive warp offsets
        if (tid == 15) s_total = sw;
    }
    __syncthreads();
    if (tid < NWORD) {
        int p = wsum[wid] + sc - c;       // exclusive prefix for this word
        unsigned m = bits[tid];
        while (m) {
            int bp = __ffs(m) - 1; m &= m - 1;
            g_sellist[b * 512 + p++] = tid * 32 + bp;
        }
    }
    if (tid == 0) g_ucnt[b] = s_total;
}

// -------- K5: gather partial sums (4 blocks per batch) --------
__global__ void __launch_bounds__(DD)
k_pool(const float* __restrict__ x) {
    int b = blockIdx.x >> 2, q = blockIdx.x & 3, tid = threadIdx.x;
    __shared__ int s_sel[128];
    int cnt = g_ucnt[b];
    int per = (cnt + 3) >> 2;
    int j0 = q * per;
    int j1 = min(cnt, j0 + per);
    int n = j1 - j0;
    if (tid < n) s_sel[tid] = g_sellist[b * 512 + j0 + tid];
    __syncthreads();

    const float* xb = x + (size_t)b * NN * DD;
    float a0 = 0.f, a1 = 0.f, a2 = 0.f, a3 = 0.f;
    int j = 0;
    for (; j + 4 <= n; j += 4) {
        a0 += xb[(size_t)s_sel[j + 0] * DD + tid];
        a1 += xb[(size_t)s_sel[j + 1] * DD + tid];
        a2 += xb[(size_t)s_sel[j + 2] * DD + tid];
        a3 += xb[(size_t)s_sel[j + 3] * DD + tid];
    }
    for (; j < n; ++j) a0 += xb[(size_t)s_sel[j] * DD + tid];
    g_part[(size_t)(b * 4 + q) * DD + tid] = (a0 + a1) + (a2 + a3);
}

// -------- block-wide sum over 512 threads --------
__device__ __forceinline__ float block_sum512(float v, float* s_red) {
    int tid = threadIdx.x;
#pragma unroll
    for (int o = 16; o; o >>= 1) v += __shfl_xor_sync(0xffffffffu, v, o);
    if ((tid & 31) == 0) s_red[tid >> 5] = v;
    __syncthreads();
    if (tid < 16) {
        float r = s_red[tid];
#pragma unroll
        for (int o = 8; o; o >>= 1) r += __shfl_xor_sync(0x0000ffffu, r, o);
        if (tid == 0) s_red[0] = r;
    }
    __syncthreads();
    float r = s_red[0];
    __syncthreads();
    return r;
}

// -------- K6: MLP + LN + SiLU + head --------
__global__ void __launch_bounds__(DD)
k_mlp(const float* __restrict__ W1, const float* __restrict__ b1,
      const float* __restrict__ gamma, const float* __restrict__ beta,
      const float* __restrict__ W2, const float* __restrict__ b2,
      float* __restrict__ out) {
    int b = blockIdx.x, tid = threadIdx.x;
    __shared__ float s_v[DD];
    __shared__ float s_red[16];
    __shared__ float s_part[16][OO];

    float cnt = (float)g_ucnt[b];
    const float* pp = g_part + (size_t)b * 4 * DD;
    float emb = ((pp[tid] + pp[DD + tid]) + (pp[2 * DD + tid] + pp[3 * DD + tid])) / cnt;
    s_v[tid] = emb;
    __syncthreads();

    float h = b1[tid];
#pragma unroll 8
    for (int k = 0; k < DD; k++)
        h = __fmaf_rn(s_v[k], W1[k * DD + tid], h);

    float mu  = block_sum512(h, s_red) * (1.0f / DD);
    float dv  = h - mu;
    float var = block_sum512(dv * dv, s_red) * (1.0f / DD);
    float vn  = dv * rsqrtf(var + 1e-5f) * gamma[tid] + beta[tid];
    float act = vn / (1.0f + __expf(-vn));  // SiLU

    float p[OO];
#pragma unroll
    for (int o = 0; o < OO; o++) p[o] = act * W2[tid * OO + o];
#pragma unroll
    for (int o = 0; o < OO; o++)
#pragma unroll
        for (int of = 16; of; of >>= 1)
            p[o] += __shfl_xor_sync(0xffffffffu, p[o], of);
    if ((tid & 31) == 0) {
#pragma unroll
        for (int o = 0; o < OO; o++) s_part[tid >> 5][o] = p[o];
    }
    __syncthreads();
    if (tid < OO) {
        float s = 0.f;
#pragma unroll
        for (int w = 0; w < 16; w++) s += s_part[w][tid];
        out[b * OO + tid] = s + b2[tid];
    }
}

extern "C" void kernel_launch(void* const* d_in, const int* in_sizes, int n_in,
                              void* d_out, int out_size) {
    const float* pos   = (const float*)d_in[0];
    const float* x     = (const float*)d_in[1];
    const float* lig   = (const float*)d_in[2];
    const float* W1    = (const float*)d_in[3];
    const float* b1    = (const float*)d_in[4];
    const float* gamma = (const float*)d_in[5];
    const float* beta  = (const float*)d_in[6];
    const float* W2    = (const float*)d_in[7];
    const float* b2    = (const float*)d_in[8];
    float* out = (float*)d_out;

    k_init<<<13, 256>>>();
    k_thresh<<<(BB * NGRP * NCHUNK * 32) / 256, 256>>>(pos, lig);   // 400 blocks
    k_collect<<<(BB * NGRP * NCHUNK * 32) / 256, 256>>>(pos, lig);  // 400 blocks
    k_select<<<(BB * LL * 32) / 256, 256>>>(pos, lig);              // 400 blocks
    k_compact<<<BB, 512>>>();
    k_pool<<<BB * 4, DD>>>(x);
    k_mlp<<<BB, DD>>>(W1, b1, gamma, beta, W2, b2, out);
}

// round 3
// speedup vs baseline: 2.3784x; 1.2014x over previous
#include <cuda_runtime.h>
#include <cstdint>

#define BB 64
#define NN 10000
#define LL 50
#define DD 512
#define OO 7
#define KNB 10
#define NGRP 5        // ligand groups per batch (10 ligs each)
#define GL 10         // ligs per group
#define NCHUNK 10     // chunks (= warps) per block
#define CHUNK 1000    // NN / NCHUNK
#define CAPS 256      // smem candidate capacity per lig
#define NWORD 313     // ceil(NN/32)

typedef unsigned long long ull;

// -------- device scratch (no allocations allowed) --------
__device__ int   g_sel10[BB * LL * KNB];
__device__ int   g_ucnt[BB];
__device__ float g_part[BB * 4 * DD];

// order-preserving float->uint transform (handles negative keys)
__device__ __forceinline__ unsigned encf(float f) {
    unsigned u = __float_as_uint(f);
    return (u & 0x80000000u) ? ~u : (u | 0x80000000u);
}
// key = 0.5*|p|^2 - p.l  (order-equivalent to |p-l|^2 for fixed l)
__device__ __forceinline__ float qof(float px, float py, float pz) {
    return 0.5f * __fmaf_rn(pz, pz, __fmaf_rn(py, py, __fmul_rn(px, px)));
}
__device__ __forceinline__ float keyf(float px, float py, float pz, float q,
                                      float lx, float ly, float lz) {
    return __fmaf_rn(pz, -lz, __fmaf_rn(py, -ly, __fmaf_rn(px, -lx, q)));
}
__device__ __forceinline__ ull umin64(ull a, ull b) { return a < b ? a : b; }
__device__ __forceinline__ ull umax64(ull a, ull b) { return a < b ? b : a; }

// full 32-lane bitonic sort, ascending (float)
__device__ __forceinline__ float bitonic_f(float v, int lane) {
#pragma unroll
    for (int k = 2; k <= 32; k <<= 1) {
#pragma unroll
        for (int o = k >> 1; o; o >>= 1) {
            float p = __shfl_xor_sync(0xffffffffu, v, o);
            bool keepMin = (((lane & o) == 0) == ((lane & k) == 0));
            v = keepMin ? fminf(v, p) : fmaxf(v, p);
        }
    }
    return v;
}
// full 32-lane bitonic sort, ascending (u64)
__device__ __forceinline__ ull bitonic_u64(ull v, int lane) {
#pragma unroll
    for (int k = 2; k <= 32; k <<= 1) {
#pragma unroll
        for (int o = k >> 1; o; o >>= 1) {
            ull p = __shfl_xor_sync(0xffffffffu, v, o);
            bool keepMin = (((lane & o) == 0) == ((lane & k) == 0));
            v = keepMin ? umin64(v, p) : umax64(v, p);
        }
    }
    return v;
}

// ===================== K1: fused threshold + collect + select =============
// block = (batch, ligand-group); warp w = chunk w of the point cloud.
__global__ void __launch_bounds__(NCHUNK * 32)
k_knn(const float* __restrict__ pos, const float* __restrict__ lig) {
    int b    = blockIdx.x / NGRP;
    int grp  = blockIdx.x % NGRP;
    int tid  = threadIdx.x;
    int ch   = tid >> 5;          // warp = chunk
    int lane = tid & 31;

    __shared__ float s_bound[NCHUNK * GL];
    __shared__ int   s_cnt[GL];
    __shared__ ull   s_cand[GL][CAPS];

    if (tid < GL) s_cnt[tid] = 0;

    // ligand coords for this group (broadcast loads)
    float lx[GL], ly[GL], lz[GL];
    const float* lp = lig + ((size_t)b * LL + grp * GL) * 3;
#pragma unroll
    for (int j = 0; j < GL; j++) {
        lx[j] = lp[j * 3 + 0]; ly[j] = lp[j * 3 + 1]; lz[j] = lp[j * 3 + 2];
    }

    const float* pp = pos + (size_t)b * NN * 3;
    const int i0 = ch * CHUNK, i1 = i0 + CHUNK;

    // ---- Phase A: per-chunk lane minima -> 10th-smallest bound ----
    float m[GL];
#pragma unroll
    for (int j = 0; j < GL; j++) m[j] = 3.4e38f;
    for (int i = i0 + lane; i < i1; i += 32) {
        float px = pp[i * 3 + 0], py = pp[i * 3 + 1], pz = pp[i * 3 + 2];
        float q = qof(px, py, pz);
#pragma unroll
        for (int j = 0; j < GL; j++)
            m[j] = fminf(m[j], keyf(px, py, pz, q, lx[j], ly[j], lz[j]));
    }
    // 10 distinct lanes (=> 10 distinct points) have minima <= sorted[9]:
    // provable upper bound on this chunk's 10th-smallest key.
#pragma unroll
    for (int j = 0; j < GL; j++) {
        float sv = bitonic_f(m[j], lane);
        float w  = __shfl_sync(0xffffffffu, sv, KNB - 1);
        if (lane == 0) s_bound[ch * GL + j] = w;
    }
    __syncthreads();

    // ---- Phase B: T0 = min over chunks; collect candidates into smem ----
    float t[GL];
#pragma unroll
    for (int j = 0; j < GL; j++) {
        float tv = s_bound[j];
#pragma unroll
        for (int c = 1; c < NCHUNK; c++) tv = fminf(tv, s_bound[c * GL + j]);
        t[j] = tv;
    }
    for (int i = i0 + lane; i < i1; i += 32) {
        float px = pp[i * 3 + 0], py = pp[i * 3 + 1], pz = pp[i * 3 + 2];
        float q = qof(px, py, pz);
#pragma unroll
        for (int j = 0; j < GL; j++) {
            float key = keyf(px, py, pz, q, lx[j], ly[j], lz[j]);
            if (key <= t[j]) {
                int p = atomicAdd(&s_cnt[j], 1);
                if (p < CAPS)
                    s_cand[j][p] = ((ull)encf(key) << 32) | (unsigned)i;
            }
        }
    }
    __syncthreads();

    // ---- Phase C: warp j selects exact top-10 for lig j ----
    int j = ch;  // NCHUNK == GL
    int cnt = s_cnt[j];
    int base_out = (b * LL + grp * GL + j) * KNB;

    if (cnt <= CAPS) {
        // running sorted-32 accumulator via bitonic merge
        ull cur = ~0ull;
        for (int s0 = 0; s0 < cnt; s0 += 32) {
            int s = s0 + lane;
            ull v = (s < cnt) ? s_cand[j][s] : ~0ull;
            v = bitonic_u64(v, lane);                       // new asc
            ull rv = __shfl_sync(0xffffffffu, v, 31 - lane); // new desc
            cur = umin64(cur, rv);                           // bitonic low-32
#pragma unroll
            for (int o = 16; o; o >>= 1) {                   // re-sort asc
                ull p = __shfl_xor_sync(0xffffffffu, cur, o);
                cur = ((lane & o) == 0) ? umin64(cur, p) : umax64(cur, p);
            }
        }
        if (lane < KNB)
            g_sel10[base_out + lane] = (int)(unsigned)(cur & 0xffffffffu);
    } else {
        // fallback: exact rescan of all N points (not expected to trigger)
        float flx = lx[j], fly = ly[j], flz = lz[j];
        ull hp[KNB];
#pragma unroll
        for (int r = 0; r < KNB; r++) hp[r] = ~0ull;
        for (int i = lane; i < NN; i += 32) {
            float px = pp[i * 3 + 0], py = pp[i * 3 + 1], pz = pp[i * 3 + 2];
            float q = qof(px, py, pz);
            ull v = ((ull)encf(keyf(px, py, pz, q, flx, fly, flz)) << 32) |
                    (unsigned)i;
            if (v < hp[KNB - 1]) {
#pragma unroll
                for (int r = 0; r < KNB; r++)
                    if (v < hp[r]) { ull tm = hp[r]; hp[r] = v; v = tm; }
            }
        }
        ull curv = hp[0];
#pragma unroll
        for (int rr = 0; rr < KNB; rr++) {
            ull w = curv;
#pragma unroll
            for (int o = 16; o; o >>= 1)
                w = umin64(w, __shfl_xor_sync(0xffffffffu, w, o));
            if (lane == 0)
                g_sel10[base_out + rr] = (int)(unsigned)(w & 0xffffffffu);
            if (curv == w) {
#pragma unroll
                for (int r = 0; r < KNB - 1; r++) hp[r] = hp[r + 1];
                hp[KNB - 1] = ~0ull;
                curv = hp[0];
            }
        }
    }
}

// ===================== K2: dedupe + gather partial sums ===================
// 4 blocks per batch; each rebuilds the bitmap (cheap) and gathers a quarter.
__global__ void __launch_bounds__(DD)
k_poolc(const float* __restrict__ x) {
    int b = blockIdx.x >> 2, q = blockIdx.x & 3, tid = threadIdx.x;
    int lane = tid & 31, wid = tid >> 5;
    __shared__ unsigned bits[320];
    __shared__ int wsum[16];
    __shared__ int s_list[512];
    __shared__ int s_total;

    if (tid < 320) bits[tid] = 0u;
    __syncthreads();
    if (tid < LL * KNB) {
        unsigned idx = (unsigned)g_sel10[b * LL * KNB + tid];
        atomicOr(&bits[idx >> 5], 1u << (idx & 31));
    }
    __syncthreads();

    int c = (tid < NWORD) ? __popc(bits[tid]) : 0;
    int sc = c;  // inclusive warp scan
#pragma unroll
    for (int o = 1; o < 32; o <<= 1) {
        int n = __shfl_up_sync(0xffffffffu, sc, o);
        if (lane >= o) sc += n;
    }
    if (lane == 31) wsum[wid] = sc;
    __syncthreads();
    if (tid < 16) {
        int w = wsum[tid], sw = w;
#pragma unroll
        for (int o = 1; o < 16; o <<= 1) {
            int n = __shfl_up_sync(0x0000ffffu, sw, o);
            if (tid >= o) sw += n;
        }
        wsum[tid] = sw - w;               // exclusive warp offsets
        if (tid == 15) s_total = sw;
    }
    __syncthreads();
    if (tid < NWORD) {
        int p = wsum[wid] + sc - c;
        unsigned mm = bits[tid];
        while (mm) {
            int bp = __ffs(mm) - 1; mm &= mm - 1;
            s_list[p++] = tid * 32 + bp;
        }
    }
    __syncthreads();

    int cnt = s_total;
    if (q == 0 && tid == 0) g_ucnt[b] = cnt;

    int per = (cnt + 3) >> 2;
    int j0 = q * per;
    int j1 = min(cnt, j0 + per);
    int n = j1 - j0;

    const float* xb = x + (size_t)b * NN * DD;
    float a0 = 0.f, a1 = 0.f, a2 = 0.f, a3 = 0.f;
    int j = 0;
    for (; j + 4 <= n; j += 4) {
        a0 += xb[(size_t)s_list[j0 + j + 0] * DD + tid];
        a1 += xb[(size_t)s_list[j0 + j + 1] * DD + tid];
        a2 += xb[(size_t)s_list[j0 + j + 2] * DD + tid];
        a3 += xb[(size_t)s_list[j0 + j + 3] * DD + tid];
    }
    for (; j < n; ++j) a0 += xb[(size_t)s_list[j0 + j] * DD + tid];
    g_part[(size_t)(b * 4 + q) * DD + tid] = (a0 + a1) + (a2 + a3);
}

// -------- block-wide sum over 512 threads --------
__device__ __forceinline__ float block_sum512(float v, float* s_red) {
    int tid = threadIdx.x;
#pragma unroll
    for (int o = 16; o; o >>= 1) v += __shfl_xor_sync(0xffffffffu, v, o);
    if ((tid & 31) == 0) s_red[tid >> 5] = v;
    __syncthreads();
    if (tid < 16) {
        float r = s_red[tid];
#pragma unroll
        for (int o = 8; o; o >>= 1) r += __shfl_xor_sync(0x0000ffffu, r, o);
        if (tid == 0) s_red[0] = r;
    }
    __syncthreads();
    float r = s_red[0];
    __syncthreads();
    return r;
}

// ===================== K3: MLP + LN + SiLU + head =========================
__global__ void __launch_bounds__(DD)
k_mlp(const float* __restrict__ W1, const float* __restrict__ b1,
      const float* __restrict__ gamma, const float* __restrict__ beta,
      const float* __restrict__ W2, const float* __restrict__ b2,
      float* __restrict__ out) {
    int b = blockIdx.x, tid = threadIdx.x;
    __shared__ float s_v[DD];
    __shared__ float s_red[16];
    __shared__ float s_part[16][OO];

    float cnt = (float)g_ucnt[b];
    const float* pp = g_part + (size_t)b * 4 * DD;
    s_v[tid] = ((pp[tid] + pp[DD + tid]) + (pp[2 * DD + tid] + pp[3 * DD + tid])) / cnt;
    __syncthreads();

    float h = b1[tid];
#pragma unroll 16
    for (int k = 0; k < DD; k++)
        h = __fmaf_rn(s_v[k], W1[k * DD + tid], h);

    float mu  = block_sum512(h, s_red) * (1.0f / DD);
    float dv  = h - mu;
    float var = block_sum512(dv * dv, s_red) * (1.0f / DD);
    float vn  = dv * rsqrtf(var + 1e-5f) * gamma[tid] + beta[tid];
    float act = vn / (1.0f + __expf(-vn));  // SiLU

    float p[OO];
#pragma unroll
    for (int o = 0; o < OO; o++) p[o] = act * W2[tid * OO + o];
#pragma unroll
    for (int o = 0; o < OO; o++)
#pragma unroll
        for (int of = 16; of; of >>= 1)
            p[o] += __shfl_xor_sync(0xffffffffu, p[o], of);
    if ((tid & 31) == 0) {
#pragma unroll
        for (int o = 0; o < OO; o++) s_part[tid >> 5][o] = p[o];
    }
    __syncthreads();
    if (tid < OO) {
        float s = 0.f;
#pragma unroll
        for (int w = 0; w < 16; w++) s += s_part[w][tid];
        out[b * OO + tid] = s + b2[tid];
    }
}

extern "C" void kernel_launch(void* const* d_in, const int* in_sizes, int n_in,
                              void* d_out, int out_size) {
    const float* pos   = (const float*)d_in[0];
    const float* x     = (const float*)d_in[1];
    const float* lig   = (const float*)d_in[2];
    const float* W1    = (const float*)d_in[3];
    const float* b1    = (const float*)d_in[4];
    const float* gamma = (const float*)d_in[5];
    const float* beta  = (const float*)d_in[6];
    const float* W2    = (const float*)d_in[7];
    const float* b2    = (const float*)d_in[8];
    float* out = (float*)d_out;

    k_knn<<<BB * NGRP, NCHUNK * 32>>>(pos, lig);   // 320 blocks x 320 thr
    k_poolc<<<BB * 4, DD>>>(x);                    // 256 blocks x 512 thr
    k_mlp<<<BB, DD>>>(W1, b1, gamma, beta, W2, b2, out);
}